// round 16
// baseline (speedup 1.0000x reference)
#include <cuda_runtime.h>
#include <cuda_fp16.h>
#include <math.h>
#include <stdint.h>

// ---------------- problem constants ----------------
#define BB   8
#define TT   1024
#define BTOK (BB*TT)          // 8192
#define N4   4
#define K3   3
#define DH   128
#define DD   896              // S*DH
#define NDD  3584             // N*D
#define HID  3584             // 4*D
#define IOD  1024
#define RNK  64
#define NH   12               // N*K heads
#define EPSF 1e-5f
#define FASCALE 0.088388347648318447f

// ---------------- device scratch ----------------
__device__ float g_beta;
__device__ int   g_slot[3];
__device__ int   g_invp[3][4];

__device__ __align__(16) __half g_h[BTOK*RNK];
__device__ __align__(16) float  g_base[(size_t)BTOK*DD];
__device__ __align__(16) __half g_z1h[(size_t)BTOK*NDD];   // z1 residual stream (fp16)
__device__ __align__(16) __half g_z2h[(size_t)BTOK*NDD];   // z2 (fp16)
__device__ __align__(16) __half g_hmh[(size_t)BTOK*NDD];   // LN outputs (fp16)
__device__ __align__(16) __half g_hidden[(size_t)BTOK*4*HID];
__device__ __align__(16) __half g_xhh[(size_t)BTOK*NH*DH];
__device__ __align__(16) __half g_q[(size_t)BB*NH*TT*DH];
__device__ __align__(16) __half g_k[(size_t)BB*NH*TT*DH];
__device__ __align__(16) __half g_v[(size_t)BB*NH*TT*DH];
__device__ __align__(16) float  g_dec4[(size_t)4*BTOK*RNK];
__device__ __align__(16) __half g_decH[BTOK*RNK];

// fp16 packed operands
__device__ __align__(16) __half g_xH   [(size_t)BTOK*IOD];
__device__ __align__(16) __half g_wbA  [(size_t)1024*IOD];  // [wb(896) ; enc_A(64) ; zeros(64)]
__device__ __align__(16) __half g_ebT  [(size_t)NDD*RNK];
__device__ __align__(16) __half g_wqT  [(size_t)K3*N4*3*DH*DH];
__device__ __align__(16) __half g_w1H  [(size_t)HID*DD];
__device__ __align__(16) __half g_w2H  [(size_t)DD*HID];
__device__ __align__(16) __half g_downH[(size_t)128*NDD];   // down padded 64->128 rows
__device__ __align__(16) __half g_upH  [(size_t)IOD*RNK];

// ---------------- low-level helpers ----------------
__device__ __forceinline__ void mma_f16(float* c, const uint32_t* a, const uint32_t* b) {
    asm volatile("mma.sync.aligned.m16n8k16.row.col.f32.f16.f16.f32 "
        "{%0,%1,%2,%3},{%4,%5,%6,%7},{%8,%9},{%0,%1,%2,%3};"
        : "+f"(c[0]), "+f"(c[1]), "+f"(c[2]), "+f"(c[3])
        : "r"(a[0]), "r"(a[1]), "r"(a[2]), "r"(a[3]), "r"(b[0]), "r"(b[1]));
}
__device__ __forceinline__ void cp16(uint32_t d, const void* g) {
    asm volatile("cp.async.cg.shared.global [%0], [%1], 16;\n" :: "r"(d), "l"(g) : "memory");
}
__device__ __forceinline__ void ldsm4(uint32_t* r, uint32_t a) {
    asm volatile("ldmatrix.sync.aligned.m8n8.x4.shared.b16 {%0,%1,%2,%3}, [%4];"
        : "=r"(r[0]), "=r"(r[1]), "=r"(r[2]), "=r"(r[3]) : "r"(a));
}
__device__ __forceinline__ void ldsm4t(uint32_t* r, uint32_t a) {
    asm volatile("ldmatrix.sync.aligned.m8n8.x4.trans.shared.b16 {%0,%1,%2,%3}, [%4];"
        : "=r"(r[0]), "=r"(r[1]), "=r"(r[2]), "=r"(r[3]) : "r"(a));
}
__device__ __forceinline__ uint32_t packh2(float a, float b) {
    __half2 h = __floats2half2_rn(a, b);
    return *(uint32_t*)&h;
}

// ---------------- scalar / table prologue ----------------
__global__ void k_scalars(const float* beta, const int* phase) {
    g_beta = *beta;
    int ph = *phase;
    int off = 0;
    const int sc[3] = {1, 2, 4};
    for (int k = 0; k < 3; k++) {
        int s = sc[k];
        int j = ph % s;
        g_slot[k] = off + j;
        off += s;
        int alpha = 4 / s;
        for (int i = 0; i < 4; i++) {
            int p = (i + alpha * j) & 3;
            g_invp[k][p] = i;
        }
    }
}

// ---------------- fused packing kernel ----------------
#define P0 4194304              // xH (half2)
#define P1 458752               // wbA rows 0..895 <- wb (half2)
#define PA 32768                // wbA rows 896..959 <- enc_A (half2)
#define PB 32768                // wbA rows 960..1023 <- zero (half2)
#define P2 1605632              // w1H (half2)
#define P3 1605632              // w2H (half2)
#define P4 32768                // upH (half2)
#define P5 229376               // ebT (half)
#define P6 589824               // wqT (half)
#define P7 458752               // downH (half, padded)
#define PTOT (P0+P1+PA+PB+P2+P3+P4+P5+P6+P7)

__global__ void k_pack(const float* __restrict__ x, const float* __restrict__ wb,
                       const float* __restrict__ w1, const float* __restrict__ w2,
                       const float* __restrict__ up, const float* __restrict__ eb,
                       const float* __restrict__ wq, const float* __restrict__ down,
                       const float* __restrict__ encA) {
    long i = (long)blockIdx.x * blockDim.x + threadIdx.x;
    if (i < P0) {
        float2 v = ((const float2*)x)[i];
        ((__half2*)g_xH)[i] = __floats2half2_rn(v.x, v.y);
        return;
    }
    i -= P0;
    if (i < P1) {
        float2 v = ((const float2*)wb)[i];
        ((__half2*)g_wbA)[i] = __floats2half2_rn(v.x, v.y);
        return;
    }
    i -= P1;
    if (i < PA) {
        float2 v = ((const float2*)encA)[i];
        ((__half2*)g_wbA)[P1 + i] = __floats2half2_rn(v.x, v.y);
        return;
    }
    i -= PA;
    if (i < PB) {
        ((__half2*)g_wbA)[P1 + PA + i] = __floats2half2_rn(0.f, 0.f);
        return;
    }
    i -= PB;
    if (i < P2) {
        float2 v = ((const float2*)w1)[i];
        ((__half2*)g_w1H)[i] = __floats2half2_rn(v.x, v.y);
        return;
    }
    i -= P2;
    if (i < P3) {
        float2 v = ((const float2*)w2)[i];
        ((__half2*)g_w2H)[i] = __floats2half2_rn(v.x, v.y);
        return;
    }
    i -= P3;
    if (i < P4) {
        float2 v = ((const float2*)up)[i];
        ((__half2*)g_upH)[i] = __floats2half2_rn(v.x, v.y);
        return;
    }
    i -= P4;
    if (i < P5) {                 // ebT: (64, 3584) -> (3584, 64)
        int n = (int)(i >> 6), r = (int)(i & 63);
        g_ebT[i] = __float2half_rn(eb[(size_t)r * NDD + n]);
        return;
    }
    i -= P5;
    if (i < P6) {                 // wqT: (bz,128,384) -> (bz,384,128)
        int bz = (int)(i / (384 * 128));
        int r = (int)(i - (long)bz * (384 * 128));
        int n = r >> 7, k = r & 127;
        g_wqT[i] = __float2half_rn(wq[(size_t)bz * 128 * 384 + (size_t)k * 384 + n]);
        return;
    }
    i -= P6;
    if (i < P7) {                 // downH: pad 64->128 rows
        int r = (int)(i / NDD);
        g_downH[i] = (r < RNK) ? __float2half_rn(down[i]) : __half(0.f);
    }
}

__global__ void k_decsum(int total) {
    int idx = blockIdx.x * blockDim.x + threadIdx.x;
    if (idx < total) {
        g_decH[idx] = __float2half_rn(
            g_dec4[idx] + g_dec4[idx + (size_t)BTOK*RNK]
          + g_dec4[idx + (size_t)2*BTOK*RNK] + g_dec4[idx + (size_t)3*BTOK*RNK]);
    }
}

// ---------------- block reductions ----------------
template<int W>
__device__ __forceinline__ float block_sum(float x, float* red) {
#pragma unroll
    for (int o = 16; o > 0; o >>= 1) x += __shfl_xor_sync(0xffffffffu, x, o);
    __syncthreads();
    if ((threadIdx.x & 31) == 0) red[threadIdx.x >> 5] = x;
    __syncthreads();
    float s = 0.f;
#pragma unroll
    for (int i = 0; i < W; i++) s += red[i];
    return s;
}

// ---------------- epilogue functors ----------------
struct EpiBaseH {   // merged: n<896 -> base (fp32), 896..959 -> h (fp16), rest discard
    __device__ void operator()(int m, int n, int, float v) const {
        if (n < DD)            g_base[(size_t)m * DD + n] = v;
        else if (n < DD + RNK) g_h[m * RNK + (n - DD)] = __float2half_rn(v);
    }
};
struct EpiDelta {   // z1 = base + beta*delta -> fp16
    __device__ void operator()(int m, int n, int, float v) const {
        int nm = n; if (nm >= 2*DD) nm -= 2*DD; if (nm >= DD) nm -= DD;
        g_z1h[(size_t)m * NDD + n] =
            __float2half_rn(g_base[(size_t)m * DD + nm] + g_beta * v);
    }
};
struct EpiQKV {
    __device__ void operator()(int m, int n, int bz, float v) const {
        int b = m >> 10, t = m & 1023;
        int kk = bz >> 2, ns = bz & 3;
        int h = g_invp[kk][ns] * 3 + kk;
        __half* dst; int e = n;
        if (e < DH)            { dst = g_q; }
        else if (e < 2*DH)     { dst = g_k; e -= DH; }
        else                   { dst = g_v; e -= 2*DH; }
        dst[(((size_t)b * NH + h) * TT + t) * DH + e] = __float2half_rn(v);
    }
};
struct EpiGelu {
    const float* b1;
    __device__ void operator()(int m, int n, int, float v) const {
        float u = v + b1[n];
        g_hidden[(size_t)m * HID + n] =
            __float2half_rn(0.5f * u * (1.f + erff(u * 0.70710678118654752f)));
    }
};
struct EpiMix2 {  // z2 = z1 + m + b2 -> fp16
    const float* b2;
    __device__ void operator()(int m, int n, int, float v) const {
        g_z2h[(size_t)m * DD + n] =
            __float2half_rn(__half2float(g_z1h[(size_t)m * DD + n]) + v + b2[n]);
    }
};
struct EpiDec4 {
    __device__ void operator()(int m, int n, int bz, float v) const {
        if (n < RNK) g_dec4[((size_t)bz * BTOK + m) * RNK + n] = v;
    }
};
struct EpiOut {
    float* out;
    __device__ void operator()(int m, int n, int, float v) const { out[(size_t)m * IOD + n] = v; }
};

// ================= flash attention (causal, d=128, T=1024) =================
#define FA_PITCH 272
#define FA_TILE  (128*FA_PITCH)        // 34816
#define FA_SMEM  (5*FA_TILE)           // 174080

__global__ void __launch_bounds__(256, 1)
k_flash() {
    extern __shared__ char fsm[];
    const int mi = 7 - blockIdx.x;     // LPT
    const int bh = blockIdx.y;
    const int m0 = mi * 128;
    const int tid = threadIdx.x, lane = tid & 31, wid = tid >> 5;
    const int wm = wid * 16;
    const int g = lane >> 3, ri = lane & 7;

    const __half* Qg = g_q + (size_t)bh * TT * DH;
    const __half* Kg = g_k + (size_t)bh * TT * DH;
    const __half* Vg = g_v + (size_t)bh * TT * DH;

    const uint32_t qb = (uint32_t)__cvta_generic_to_shared(fsm);

    auto load_tile = [&](uint32_t dstbase, const __half* src, int t0) {
        int row = tid >> 1, half = tid & 1;
        const __half* sp = src + (size_t)(t0 + row) * DH + half * 64;
        uint32_t dp = dstbase + (uint32_t)row * FA_PITCH + half * 128;
#pragma unroll
        for (int i = 0; i < 8; i++) cp16(dp + i * 16, sp + i * 8);
    };

    load_tile(qb, Qg, m0);
    load_tile(qb + FA_TILE, Kg, 0);
    load_tile(qb + 3*FA_TILE, Vg, 0);
    asm volatile("cp.async.commit_group;\n" ::);
    if (mi >= 1) {
        load_tile(qb + 2*FA_TILE, Kg, 128);
        load_tile(qb + 4*FA_TILE, Vg, 128);
        asm volatile("cp.async.commit_group;\n" ::);
    }

    float o[16][4];
#pragma unroll
    for (int i = 0; i < 16; i++)
#pragma unroll
        for (int r = 0; r < 4; r++) o[i][r] = 0.f;
    float m1 = -1e30f, m2 = -1e30f, l1 = 0.f, l2 = 0.f;
    uint32_t q[8][4];
    bool qloaded = false;

    const int tr1 = wm + (lane >> 2);
    const int cbase = (lane & 3) * 2;

    for (int j = 0; j <= mi; j++) {
        if (j + 1 <= mi) asm volatile("cp.async.wait_group 1;\n" ::: "memory");
        else             asm volatile("cp.async.wait_group 0;\n" ::: "memory");
        __syncthreads();
        if (!qloaded) {
#pragma unroll
            for (int kt = 0; kt < 8; kt++) {
                uint32_t ad = qb + (uint32_t)(wm + (g & 1) * 8 + ri) * FA_PITCH
                                 + kt * 32 + (g >> 1) * 16;
                ldsm4(q[kt], ad);
            }
            qloaded = true;
        }
        uint32_t kb = qb + FA_TILE + (uint32_t)(j & 1) * FA_TILE;
        uint32_t vb = qb + 3*FA_TILE + (uint32_t)(j & 1) * FA_TILE;

        float c[16][4];
#pragma unroll
        for (int i = 0; i < 16; i++) { c[i][0]=0.f; c[i][1]=0.f; c[i][2]=0.f; c[i][3]=0.f; }
#pragma unroll
        for (int kt = 0; kt < 8; kt++) {
#pragma unroll
            for (int np = 0; np < 8; np++) {
                uint32_t rr[4], b0[2], b1[2];
                uint32_t bd = kb + (uint32_t)(np * 16 + (g & 1) * 8 + ri) * FA_PITCH
                                 + kt * 32 + (g >> 1) * 16;
                ldsm4(rr, bd);
                b0[0] = rr[0]; b0[1] = rr[2];
                b1[0] = rr[1]; b1[1] = rr[3];
                mma_f16(c[np * 2],     q[kt], b0);
                mma_f16(c[np * 2 + 1], q[kt], b1);
            }
        }

        const bool diag = (j == mi);
        float mx1 = -1e30f, mx2 = -1e30f;
#pragma unroll
        for (int nt = 0; nt < 16; nt++) {
            int cn = nt * 8 + cbase;
            float s0 = c[nt][0] * FASCALE, s1 = c[nt][1] * FASCALE;
            float s2 = c[nt][2] * FASCALE, s3 = c[nt][3] * FASCALE;
            if (diag) {
                if (cn     > tr1)     s0 = -1e30f;
                if (cn + 1 > tr1)     s1 = -1e30f;
                if (cn     > tr1 + 8) s2 = -1e30f;
                if (cn + 1 > tr1 + 8) s3 = -1e30f;
            }
            c[nt][0] = s0; c[nt][1] = s1; c[nt][2] = s2; c[nt][3] = s3;
            mx1 = fmaxf(mx1, fmaxf(s0, s1));
            mx2 = fmaxf(mx2, fmaxf(s2, s3));
        }
        mx1 = fmaxf(mx1, __shfl_xor_sync(0xffffffffu, mx1, 1));
        mx1 = fmaxf(mx1, __shfl_xor_sync(0xffffffffu, mx1, 2));
        mx2 = fmaxf(mx2, __shfl_xor_sync(0xffffffffu, mx2, 1));
        mx2 = fmaxf(mx2, __shfl_xor_sync(0xffffffffu, mx2, 2));

        float m1n = fmaxf(m1, mx1), m2n = fmaxf(m2, mx2);
        float corr1 = __expf(m1 - m1n), corr2 = __expf(m2 - m2n);
        float s1sum = 0.f, s2sum = 0.f;
#pragma unroll
        for (int nt = 0; nt < 16; nt++) {
            c[nt][0] = __expf(c[nt][0] - m1n);
            c[nt][1] = __expf(c[nt][1] - m1n);
            c[nt][2] = __expf(c[nt][2] - m2n);
            c[nt][3] = __expf(c[nt][3] - m2n);
            s1sum += c[nt][0] + c[nt][1];
            s2sum += c[nt][2] + c[nt][3];
        }
        s1sum += __shfl_xor_sync(0xffffffffu, s1sum, 1);
        s1sum += __shfl_xor_sync(0xffffffffu, s1sum, 2);
        s2sum += __shfl_xor_sync(0xffffffffu, s2sum, 1);
        s2sum += __shfl_xor_sync(0xffffffffu, s2sum, 2);
        l1 = l1 * corr1 + s1sum;
        l2 = l2 * corr2 + s2sum;
        m1 = m1n; m2 = m2n;
#pragma unroll
        for (int nt = 0; nt < 16; nt++) {
            o[nt][0] *= corr1; o[nt][1] *= corr1;
            o[nt][2] *= corr2; o[nt][3] *= corr2;
        }

#pragma unroll
        for (int kt = 0; kt < 8; kt++) {
            uint32_t a[4];
            a[0] = packh2(c[2*kt][0],   c[2*kt][1]);
            a[1] = packh2(c[2*kt][2],   c[2*kt][3]);
            a[2] = packh2(c[2*kt+1][0], c[2*kt+1][1]);
            a[3] = packh2(c[2*kt+1][2], c[2*kt+1][3]);
#pragma unroll
            for (int np = 0; np < 8; np++) {
                uint32_t rr[4], b0[2], b1[2];
                uint32_t bd = vb + (uint32_t)(kt * 16 + (g >> 1) * 8 + ri) * FA_PITCH
                                 + (np * 16 + (g & 1) * 8) * 2;
                ldsm4t(rr, bd);
                b0[0] = rr[0]; b0[1] = rr[2];
                b1[0] = rr[1]; b1[1] = rr[3];
                mma_f16(o[np * 2],     a, b0);
                mma_f16(o[np * 2 + 1], a, b1);
            }
        }
        __syncthreads();
        if (j + 2 <= mi) {
            load_tile(qb + FA_TILE + (uint32_t)(j & 1) * FA_TILE,   Kg, (j + 2) * 128);
            load_tile(qb + 3*FA_TILE + (uint32_t)(j & 1) * FA_TILE, Vg, (j + 2) * 128);
            asm volatile("cp.async.commit_group;\n" ::);
        }
    }

    // ---- epilogue: z1 += O/l  (fp16 half2 RMW; disjoint addresses per CTA) ----
    float inv1 = 1.f / l1, inv2 = 1.f / l2;
    int b = bh / NH, h = bh % NH;
    int kk2 = h % 3, nn = h / 3;
    int slot = g_slot[kk2];
    int gm1 = m0 + tr1;
#pragma unroll
    for (int nt = 0; nt < 16; nt++) {
        int e = slot * DH + nt * 8 + cbase;
        size_t i1 = (((size_t)(b * TT + gm1))     * N4 + nn) * DD + e;
        size_t i2 = (((size_t)(b * TT + gm1 + 8)) * N4 + nn) * DD + e;
        __half2* q1 = (__half2*)(g_z1h + i1);
        __half2* q2 = (__half2*)(g_z1h + i2);
        float2 c1 = __half22float2(*q1);
        float2 c2 = __half22float2(*q2);
        *q1 = __floats2half2_rn(c1.x + o[nt][0] * inv1, c1.y + o[nt][1] * inv1);
        *q2 = __floats2half2_rn(c2.x + o[nt][2] * inv2, c2.y + o[nt][3] * inv2);
    }
}

// ================= fp16 HMMA NT GEMM (BK=32, 3-stage, 8 warps x 32x64) =================
#define H3_TILE  10240
#define H3_STAGE (2*H3_TILE)
#define H3_SMEM  (3*H3_STAGE)

template<class Epi>
__global__ void __launch_bounds__(256, 2)
hgemm(const __half* __restrict__ A, const __half* __restrict__ B,
      int M, int N, int Kd, int lda, int ldb, long sA, long sB, Epi epi)
{
    extern __shared__ char hsm[];
    const int bz = blockIdx.z;
    A += (size_t)bz * sA;
    B += (size_t)bz * sB;
    const int m0 = blockIdx.y * 128, n0 = blockIdx.x * 128;
    const int tid = threadIdx.x;
    const int lane = tid & 31, wid = tid >> 5;
    const int wm = (wid & 3) * 32, wn = (wid >> 2) * 64;

    float c[16][4];
#pragma unroll
    for (int i = 0; i < 16; i++)
#pragma unroll
        for (int j = 0; j < 4; j++) c[i][j] = 0.f;

    {
        int nt = Kd >> 5;
        auto issue = [&](int t) {
            uint32_t base_b = (uint32_t)__cvta_generic_to_shared(hsm + (t % 3) * H3_STAGE);
            const __half* p;
            uint32_t dst;
            if (tid < 128) {
                p = A + (size_t)(m0 + tid) * lda + t * 32;
                dst = base_b + (uint32_t)tid * 80;
            } else {
                p = B + (size_t)(n0 + tid - 128) * ldb + t * 32;
                dst = base_b + H3_TILE + (uint32_t)(tid - 128) * 80;
            }
#pragma unroll
            for (int i = 0; i < 4; i++) cp16(dst + i * 16, p + i * 8);
            asm volatile("cp.async.commit_group;\n" ::);
        };

        issue(0);
        if (nt > 1) issue(1);
        const int g = lane >> 3, ri = lane & 7;
        for (int t = 0; t < nt; t++) {
            if (t == nt - 1) asm volatile("cp.async.wait_group 0;\n" ::: "memory");
            else             asm volatile("cp.async.wait_group 1;\n" ::: "memory");
            __syncthreads();
            if (t + 2 < nt) issue(t + 2);

            uint32_t as_b = (uint32_t)__cvta_generic_to_shared(hsm + (t % 3) * H3_STAGE);
            uint32_t bs_b = as_b + H3_TILE;
#pragma unroll
            for (int ks = 0; ks < 2; ks++) {
                uint32_t a[2][4];
#pragma unroll
                for (int mt = 0; mt < 2; mt++) {
                    uint32_t ad = as_b + (uint32_t)(wm + mt * 16 + (g & 1) * 8 + ri) * 80
                                       + ks * 32 + (g >> 1) * 16;
                    ldsm4(a[mt], ad);
                }
#pragma unroll
                for (int np = 0; np < 4; np++) {
                    uint32_t rr[4], b0[2], b1[2];
                    uint32_t bd = bs_b + (uint32_t)(wn + np * 16 + (g & 1) * 8 + ri) * 80
                                       + ks * 32 + (g >> 1) * 16;
                    ldsm4(rr, bd);
                    b0[0] = rr[0]; b0[1] = rr[2];
                    b1[0] = rr[1]; b1[1] = rr[3];
#pragma unroll
                    for (int mt = 0; mt < 2; mt++) {
                        mma_f16(c[mt * 8 + 2*np],     a[mt], b0);
                        mma_f16(c[mt * 8 + 2*np + 1], a[mt], b1);
                    }
                }
            }
        }
    }
#pragma unroll
    for (int mt = 0; mt < 2; mt++)
#pragma unroll
        for (int nt8 = 0; nt8 < 8; nt8++)
#pragma unroll
            for (int r = 0; r < 4; r++) {
                int gm = m0 + wm + mt * 16 + (lane >> 2) + (r >> 1) * 8;
                int gn = n0 + wn + nt8 * 8 + (lane & 3) * 2 + (r & 1);
                epi(gm, gn, bz, c[mt * 8 + nt8][r]);
            }
}

// ---------------- LN over 128 per (bt, k, n) -> x_head (fp16 in/out) ----------------
__global__ void k_ln_head(const float* __restrict__ sc, const float* __restrict__ bi) {
    int bt = blockIdx.x, z = blockIdx.y;
    int kk = z >> 2, n = z & 3;
    int ns = g_invp[kk][n];
    int slot = g_slot[kk];
    const __half* src = g_z1h + ((size_t)bt * 4 + ns) * DD + slot * DH;
    int tid = threadIdx.x;
    __shared__ float red[4];
    float v = __half2float(src[tid]);
    float mu = block_sum<4>(v, red) * (1.f / 128.f);
    float d = v - mu;
    float var = block_sum<4>(d * d, red) * (1.f / 128.f);
    g_xhh[((size_t)bt * NH + z) * DH + tid] =
        __float2half_rn(d * rsqrtf(var + EPSF) * sc[tid] + bi[tid]);
}

// ---------------- LN over 896 (fp16 in/out, feeds mixer1) ----------------
__global__ void k_ln_mixer(const float* __restrict__ sc, const float* __restrict__ bi) {
    __shared__ float red[8];
    size_t row = blockIdx.x;
    const __half* src = g_z1h + row * DD;
    __half* dst = g_hmh + row * DD;
    int tid = threadIdx.x;
    float v[4];
    float s = 0.f;
#pragma unroll
    for (int i = 0; i < 4; i++) {
        int c = tid + i * 256;
        v[i] = (c < DD) ? __half2float(src[c]) : 0.f;
        s += v[i];
    }
    s = block_sum<8>(s, red);
    float mu = s * (1.f / 896.f);
    float q = 0.f;
#pragma unroll
    for (int i = 0; i < 4; i++) {
        int c = tid + i * 256;
        if (c < DD) { float d = v[i] - mu; q += d * d; }
    }
    q = block_sum<8>(q, red);
    float r = rsqrtf(q * (1.f / 896.f) + EPSF);
#pragma unroll
    for (int i = 0; i < 4; i++) {
        int c = tid + i * 256;
        if (c < DD) dst[c] = __float2half_rn((v[i] - mu) * r * sc[c] + bi[c]);
    }
}

// ---------------- LN over 3584 (fp16 in from z2h, fp16 out to g_hmh) ----------------
__global__ void k_ln_dec(const float* __restrict__ sc, const float* __restrict__ bi) {
    __shared__ float red[8];
    size_t row = blockIdx.x;
    const __half* src = g_z2h + row * NDD;
    __half* dst = g_hmh + row * NDD;
    int tid = threadIdx.x;
    float v[14];
    float s = 0.f;
#pragma unroll
    for (int i = 0; i < 14; i++) { v[i] = __half2float(src[tid + i * 256]); s += v[i]; }
    s = block_sum<8>(s, red);
    float mu = s * (1.f / 3584.f);
    float q = 0.f;
#pragma unroll
    for (int i = 0; i < 14; i++) { float d = v[i] - mu; q += d * d; }
    q = block_sum<8>(q, red);
    float r = rsqrtf(q * (1.f / 3584.f) + EPSF);
#pragma unroll
    for (int i = 0; i < 14; i++) {
        int c = tid + i * 256;
        dst[c] = __float2half_rn((v[i] - mu) * r * sc[c] + bi[c]);
    }
}

// ---------------- host launch ----------------
static inline void* sym_addr(const void* symbol) {
    void* p = nullptr;
    cudaGetSymbolAddress(&p, symbol);
    return p;
}

extern "C" void kernel_launch(void* const* d_in, const int* in_sizes, int n_in,
                              void* d_out, int out_size) {
    (void)in_sizes; (void)n_in; (void)out_size;
    const float* x          = (const float*)d_in[0];
    const float* enc_base_w = (const float*)d_in[1];
    const float* enc_A_w    = (const float*)d_in[2];
    const float* enc_B      = (const float*)d_in[3];
    const float* enc_beta   = (const float*)d_in[4];
    const float* Wqkv       = (const float*)d_in[5];
    const float* ln_attn_s  = (const float*)d_in[6];
    const float* ln_attn_b  = (const float*)d_in[7];
    const float* ln_mix_s   = (const float*)d_in[8];
    const float* ln_mix_b   = (const float*)d_in[9];
    const float* w1         = (const float*)d_in[10];
    const float* b1         = (const float*)d_in[11];
    const float* w2         = (const float*)d_in[12];
    const float* b2         = (const float*)d_in[13];
    const float* dls        = (const float*)d_in[14];
    const float* dlb        = (const float*)d_in[15];
    const float* down       = (const float*)d_in[16];
    const float* up         = (const float*)d_in[17];
    const int*   phase      = (const int*)d_in[18];
    float* out = (float*)d_out;

    __half* p_h    = (__half*)sym_addr(g_h);
    __half* p_hmh  = (__half*)sym_addr(g_hmh);
    __half* p_hid  = (__half*)sym_addr(g_hidden);
    __half* p_xhh  = (__half*)sym_addr(g_xhh);
    __half* p_decH = (__half*)sym_addr(g_decH);
    __half* p_xH   = (__half*)sym_addr(g_xH);
    __half* p_wbA  = (__half*)sym_addr(g_wbA);
    __half* p_ebT  = (__half*)sym_addr(g_ebT);
    __half* p_wqT  = (__half*)sym_addr(g_wqT);
    __half* p_w1H  = (__half*)sym_addr(g_w1H);
    __half* p_w2H  = (__half*)sym_addr(g_w2H);
    __half* p_down = (__half*)sym_addr(g_downH);
    __half* p_upH  = (__half*)sym_addr(g_upH);

    // dynamic smem caps (idempotent)
    cudaFuncSetAttribute(hgemm<EpiBaseH>, cudaFuncAttributeMaxDynamicSharedMemorySize, H3_SMEM);
    cudaFuncSetAttribute(hgemm<EpiDelta>, cudaFuncAttributeMaxDynamicSharedMemorySize, H3_SMEM);
    cudaFuncSetAttribute(hgemm<EpiQKV  >, cudaFuncAttributeMaxDynamicSharedMemorySize, H3_SMEM);
    cudaFuncSetAttribute(hgemm<EpiGelu >, cudaFuncAttributeMaxDynamicSharedMemorySize, H3_SMEM);
    cudaFuncSetAttribute(hgemm<EpiMix2 >, cudaFuncAttributeMaxDynamicSharedMemorySize, H3_SMEM);
    cudaFuncSetAttribute(hgemm<EpiDec4 >, cudaFuncAttributeMaxDynamicSharedMemorySize, H3_SMEM);
    cudaFuncSetAttribute(hgemm<EpiOut  >, cudaFuncAttributeMaxDynamicSharedMemorySize, H3_SMEM);
    cudaFuncSetAttribute(k_flash, cudaFuncAttributeMaxDynamicSharedMemorySize, FA_SMEM);

    // 0. scalars + phase tables
    k_scalars<<<1, 1>>>(enc_beta, phase);

    // 1. fused packing (single launch)
    k_pack<<<(PTOT + 255)/256, 256>>>(x, enc_base_w, w1, w2, up, enc_B, Wqkv, down, enc_A_w);

    // 2. [base | h] = x @ [wb ; enc_A]^T  (merged)
    hgemm<<<dim3(8, 64, 1), 256, H3_SMEM>>>(
        p_xH, p_wbA, BTOK, 1024, IOD, IOD, IOD, 0, 0, EpiBaseH{});

    // 3. z1 = base + beta*(h @ enc_B)  (fp16 NT, K=64, fp16 z1 out)
    hgemm<<<dim3(28, 64, 1), 256, H3_SMEM>>>(
        p_h, p_ebT, BTOK, NDD, RNK, RNK, RNK, 0, 0, EpiDelta{});

    // 4. LN over slot heads -> x_head (fp16)
    k_ln_head<<<dim3(BTOK, NH), 128>>>(ln_attn_s, ln_attn_b);

    // 5. qkv (NT, batched 12)
    hgemm<<<dim3(3, 64, 12), 256, H3_SMEM>>>(
        p_xhh, p_wqT, BTOK, 3 * DH, DH, NH * DH, DH,
        (long)DH, (long)(3 * DH) * DH, EpiQKV{});

    // 6. flash attention (causal) -> fp16 RMW into z1
    k_flash<<<dim3(8, BB * NH), 256, FA_SMEM>>>();

    // 7. mixer LN -> fp16
    k_ln_mixer<<<dim3(BTOK * N4), 256>>>(ln_mix_s, ln_mix_b);

    // 8. hidden = gelu(hm @ w1.T + b1)  (NT)
    hgemm<<<dim3(28, 256, 1), 256, H3_SMEM>>>(
        p_hmh, p_w1H, BTOK * N4, HID, DD, DD, DD, 0, 0, EpiGelu{b1});

    // 9. z2 = z1 + hidden @ w2.T + b2  (NT, fp16 out)
    hgemm<<<dim3(7, 256, 1), 256, H3_SMEM>>>(
        p_hid, p_w2H, BTOK * N4, DD, HID, HID, HID, 0, 0, EpiMix2{b2});

    // 10. decoder LN (fp16 in/out)
    k_ln_dec<<<dim3(BTOK), 256>>>(dls, dlb);

    // 11. dec partials = catln @ down^T  (fp16 NT, 4-way split-K)
    hgemm<<<dim3(1, 64, 4), 256, H3_SMEM>>>(
        p_hmh, p_down, BTOK, 128, NDD / 4, NDD, NDD,
        (long)(NDD / 4), (long)(NDD / 4), EpiDec4{});

    // 11b. dec = sum of 4 split partials -> fp16
    k_decsum<<<(BTOK*RNK + 255)/256, 256>>>(BTOK*RNK);

    // 12. y = dec @ up^T  (fp16 NT, K=64, fp32 out)
    hgemm<<<dim3(8, 64, 1), 256, H3_SMEM>>>(
        p_decH, p_upH, BTOK, IOD, RNK, RNK, RNK, 0, 0, EpiOut{out});
}

// round 17
// speedup vs baseline: 1.0878x; 1.0878x over previous
#include <cuda_runtime.h>
#include <cuda_fp16.h>
#include <math.h>
#include <stdint.h>

// ---------------- problem constants ----------------
#define BB   8
#define TT   1024
#define BTOK (BB*TT)          // 8192
#define N4   4
#define K3   3
#define DH   128
#define DD   896              // S*DH
#define NDD  3584             // N*D
#define HID  3584             // 4*D
#define IOD  1024
#define RNK  64
#define NH   12               // N*K heads
#define EPSF 1e-5f
#define FASCALE 0.088388347648318447f

// ---------------- device scratch ----------------
__device__ float g_beta;
__device__ int   g_slot[3];
__device__ int   g_invp[3][4];

__device__ __align__(16) __half g_h[BTOK*RNK];
__device__ __align__(16) float  g_base[(size_t)BTOK*DD];
__device__ __align__(16) float  g_z1[(size_t)BTOK*NDD];
__device__ __align__(16) __half g_z2h[(size_t)BTOK*NDD];   // z2 (fp16)
__device__ __align__(16) __half g_hmh[(size_t)BTOK*NDD];   // LN outputs (fp16)
__device__ __align__(16) __half g_hidden[(size_t)BTOK*4*HID];
__device__ __align__(16) __half g_xhh[(size_t)BTOK*NH*DH];
__device__ __align__(16) __half g_q[(size_t)BB*NH*TT*DH];
__device__ __align__(16) __half g_k[(size_t)BB*NH*TT*DH];
__device__ __align__(16) __half g_v[(size_t)BB*NH*TT*DH];
__device__ __align__(16) float  g_dec4[(size_t)4*BTOK*RNK];
__device__ __align__(16) __half g_decH[BTOK*RNK];

// fp16 packed operands
__device__ __align__(16) __half g_xH   [(size_t)BTOK*IOD];
__device__ __align__(16) __half g_wbA  [(size_t)1024*IOD];  // [wb(896) ; enc_A(64) ; zeros(64)]
__device__ __align__(16) __half g_ebT  [(size_t)NDD*RNK];
__device__ __align__(16) __half g_wqT  [(size_t)K3*N4*3*DH*DH];
__device__ __align__(16) __half g_w1H  [(size_t)HID*DD];
__device__ __align__(16) __half g_w2H  [(size_t)DD*HID];
__device__ __align__(16) __half g_downH[(size_t)128*NDD];   // down padded 64->128 rows
__device__ __align__(16) __half g_upH  [(size_t)IOD*RNK];

// ---------------- low-level helpers ----------------
__device__ __forceinline__ void mma_f16(float* c, const uint32_t* a, const uint32_t* b) {
    asm volatile("mma.sync.aligned.m16n8k16.row.col.f32.f16.f16.f32 "
        "{%0,%1,%2,%3},{%4,%5,%6,%7},{%8,%9},{%0,%1,%2,%3};"
        : "+f"(c[0]), "+f"(c[1]), "+f"(c[2]), "+f"(c[3])
        : "r"(a[0]), "r"(a[1]), "r"(a[2]), "r"(a[3]), "r"(b[0]), "r"(b[1]));
}
__device__ __forceinline__ void cp16(uint32_t d, const void* g) {
    asm volatile("cp.async.cg.shared.global [%0], [%1], 16;\n" :: "r"(d), "l"(g) : "memory");
}
__device__ __forceinline__ void ldsm4(uint32_t* r, uint32_t a) {
    asm volatile("ldmatrix.sync.aligned.m8n8.x4.shared.b16 {%0,%1,%2,%3}, [%4];"
        : "=r"(r[0]), "=r"(r[1]), "=r"(r[2]), "=r"(r[3]) : "r"(a));
}
__device__ __forceinline__ void ldsm4t(uint32_t* r, uint32_t a) {
    asm volatile("ldmatrix.sync.aligned.m8n8.x4.trans.shared.b16 {%0,%1,%2,%3}, [%4];"
        : "=r"(r[0]), "=r"(r[1]), "=r"(r[2]), "=r"(r[3]) : "r"(a));
}
__device__ __forceinline__ uint32_t packh2(float a, float b) {
    __half2 h = __floats2half2_rn(a, b);
    return *(uint32_t*)&h;
}

// ---------------- scalar / table prologue ----------------
__global__ void k_scalars(const float* beta, const int* phase) {
    g_beta = *beta;
    int ph = *phase;
    int off = 0;
    const int sc[3] = {1, 2, 4};
    for (int k = 0; k < 3; k++) {
        int s = sc[k];
        int j = ph % s;
        g_slot[k] = off + j;
        off += s;
        int alpha = 4 / s;
        for (int i = 0; i < 4; i++) {
            int p = (i + alpha * j) & 3;
            g_invp[k][p] = i;
        }
    }
}

// ---------------- fused packing kernel ----------------
#define P0 4194304              // xH (half2)
#define P1 458752               // wbA rows 0..895 <- wb (half2)
#define PA 32768                // wbA rows 896..959 <- enc_A (half2)
#define PB 32768                // wbA rows 960..1023 <- zero (half2)
#define P2 1605632              // w1H (half2)
#define P3 1605632              // w2H (half2)
#define P4 32768                // upH (half2)
#define P5 229376               // ebT (half)
#define P6 589824               // wqT (half)
#define P7 458752               // downH (half, padded)
#define PTOT (P0+P1+PA+PB+P2+P3+P4+P5+P6+P7)

__global__ void k_pack(const float* __restrict__ x, const float* __restrict__ wb,
                       const float* __restrict__ w1, const float* __restrict__ w2,
                       const float* __restrict__ up, const float* __restrict__ eb,
                       const float* __restrict__ wq, const float* __restrict__ down,
                       const float* __restrict__ encA) {
    long i = (long)blockIdx.x * blockDim.x + threadIdx.x;
    if (i < P0) {
        float2 v = ((const float2*)x)[i];
        ((__half2*)g_xH)[i] = __floats2half2_rn(v.x, v.y);
        return;
    }
    i -= P0;
    if (i < P1) {
        float2 v = ((const float2*)wb)[i];
        ((__half2*)g_wbA)[i] = __floats2half2_rn(v.x, v.y);
        return;
    }
    i -= P1;
    if (i < PA) {
        float2 v = ((const float2*)encA)[i];
        ((__half2*)g_wbA)[P1 + i] = __floats2half2_rn(v.x, v.y);
        return;
    }
    i -= PA;
    if (i < PB) {
        ((__half2*)g_wbA)[P1 + PA + i] = __floats2half2_rn(0.f, 0.f);
        return;
    }
    i -= PB;
    if (i < P2) {
        float2 v = ((const float2*)w1)[i];
        ((__half2*)g_w1H)[i] = __floats2half2_rn(v.x, v.y);
        return;
    }
    i -= P2;
    if (i < P3) {
        float2 v = ((const float2*)w2)[i];
        ((__half2*)g_w2H)[i] = __floats2half2_rn(v.x, v.y);
        return;
    }
    i -= P3;
    if (i < P4) {
        float2 v = ((const float2*)up)[i];
        ((__half2*)g_upH)[i] = __floats2half2_rn(v.x, v.y);
        return;
    }
    i -= P4;
    if (i < P5) {                 // ebT: (64, 3584) -> (3584, 64)
        int n = (int)(i >> 6), r = (int)(i & 63);
        g_ebT[i] = __float2half_rn(eb[(size_t)r * NDD + n]);
        return;
    }
    i -= P5;
    if (i < P6) {                 // wqT: (bz,128,384) -> (bz,384,128)
        int bz = (int)(i / (384 * 128));
        int r = (int)(i - (long)bz * (384 * 128));
        int n = r >> 7, k = r & 127;
        g_wqT[i] = __float2half_rn(wq[(size_t)bz * 128 * 384 + (size_t)k * 384 + n]);
        return;
    }
    i -= P6;
    if (i < P7) {                 // downH: pad 64->128 rows
        int r = (int)(i / NDD);
        g_downH[i] = (r < RNK) ? __float2half_rn(down[i]) : __half(0.f);
    }
}

__global__ void k_decsum(int total) {
    int idx = blockIdx.x * blockDim.x + threadIdx.x;
    if (idx < total) {
        g_decH[idx] = __float2half_rn(
            g_dec4[idx] + g_dec4[idx + (size_t)BTOK*RNK]
          + g_dec4[idx + (size_t)2*BTOK*RNK] + g_dec4[idx + (size_t)3*BTOK*RNK]);
    }
}

// ---------------- block reductions ----------------
template<int W>
__device__ __forceinline__ float block_sum(float x, float* red) {
#pragma unroll
    for (int o = 16; o > 0; o >>= 1) x += __shfl_xor_sync(0xffffffffu, x, o);
    __syncthreads();
    if ((threadIdx.x & 31) == 0) red[threadIdx.x >> 5] = x;
    __syncthreads();
    float s = 0.f;
#pragma unroll
    for (int i = 0; i < W; i++) s += red[i];
    return s;
}

// ---------------- pair epilogue functors: (m, n, bz, v0@n, v1@n+1) ----------------
struct EpiBaseH {   // merged: n<896 -> base (fp32), 896..959 -> h (fp16)
    __device__ void operator()(int m, int n, int, float v0, float v1) const {
        if (n < DD)
            *(float2*)(g_base + (size_t)m * DD + n) = make_float2(v0, v1);
        else if (n < DD + RNK)
            *(__half2*)(g_h + m * RNK + (n - DD)) = __floats2half2_rn(v0, v1);
    }
};
struct EpiDelta {   // z1 = base + beta*delta (fp32, float2 store)
    __device__ void operator()(int m, int n, int, float v0, float v1) const {
        int nm = n; if (nm >= 2*DD) nm -= 2*DD; if (nm >= DD) nm -= DD;
        float2 b = *(const float2*)(g_base + (size_t)m * DD + nm);
        *(float2*)(g_z1 + (size_t)m * NDD + n) =
            make_float2(b.x + g_beta * v0, b.y + g_beta * v1);
    }
};
struct EpiQKV {
    __device__ void operator()(int m, int n, int bz, float v0, float v1) const {
        int b = m >> 10, t = m & 1023;
        int kk = bz >> 2, ns = bz & 3;
        int h = g_invp[kk][ns] * 3 + kk;
        __half* dst; int e = n;
        if (e < DH)            { dst = g_q; }
        else if (e < 2*DH)     { dst = g_k; e -= DH; }
        else                   { dst = g_v; e -= 2*DH; }
        *(__half2*)(dst + (((size_t)b * NH + h) * TT + t) * DH + e) =
            __floats2half2_rn(v0, v1);
    }
};
struct EpiGelu {
    const float* b1;
    __device__ void operator()(int m, int n, int, float v0, float v1) const {
        float u0 = v0 + b1[n], u1 = v1 + b1[n + 1];
        float g0 = 0.5f * u0 * (1.f + erff(u0 * 0.70710678118654752f));
        float g1 = 0.5f * u1 * (1.f + erff(u1 * 0.70710678118654752f));
        *(__half2*)(g_hidden + (size_t)m * HID + n) = __floats2half2_rn(g0, g1);
    }
};
struct EpiMix2 {  // z2 = z1 + m + b2 -> fp16 (half2 store)
    const float* b2;
    __device__ void operator()(int m, int n, int, float v0, float v1) const {
        float2 z = *(const float2*)(g_z1 + (size_t)m * DD + n);
        *(__half2*)(g_z2h + (size_t)m * DD + n) =
            __floats2half2_rn(z.x + v0 + b2[n], z.y + v1 + b2[n + 1]);
    }
};
struct EpiDec4 {
    __device__ void operator()(int m, int n, int bz, float v0, float v1) const {
        if (n < RNK)
            *(float2*)(g_dec4 + ((size_t)bz * BTOK + m) * RNK + n) = make_float2(v0, v1);
    }
};
struct EpiOut {
    float* out;
    __device__ void operator()(int m, int n, int, float v0, float v1) const {
        *(float2*)(out + (size_t)m * IOD + n) = make_float2(v0, v1);
    }
};

// ================= flash attention (causal, d=128, T=1024) =================
#define FA_PITCH 272
#define FA_TILE  (128*FA_PITCH)        // 34816
#define FA_SMEM  (5*FA_TILE)           // 174080

__global__ void __launch_bounds__(256, 1)
k_flash() {
    extern __shared__ char fsm[];
    const int mi = 7 - blockIdx.x;     // LPT
    const int bh = blockIdx.y;
    const int m0 = mi * 128;
    const int tid = threadIdx.x, lane = tid & 31, wid = tid >> 5;
    const int wm = wid * 16;
    const int g = lane >> 3, ri = lane & 7;

    const __half* Qg = g_q + (size_t)bh * TT * DH;
    const __half* Kg = g_k + (size_t)bh * TT * DH;
    const __half* Vg = g_v + (size_t)bh * TT * DH;

    const uint32_t qb = (uint32_t)__cvta_generic_to_shared(fsm);

    auto load_tile = [&](uint32_t dstbase, const __half* src, int t0) {
        int row = tid >> 1, half = tid & 1;
        const __half* sp = src + (size_t)(t0 + row) * DH + half * 64;
        uint32_t dp = dstbase + (uint32_t)row * FA_PITCH + half * 128;
#pragma unroll
        for (int i = 0; i < 8; i++) cp16(dp + i * 16, sp + i * 8);
    };

    load_tile(qb, Qg, m0);
    load_tile(qb + FA_TILE, Kg, 0);
    load_tile(qb + 3*FA_TILE, Vg, 0);
    asm volatile("cp.async.commit_group;\n" ::);
    if (mi >= 1) {
        load_tile(qb + 2*FA_TILE, Kg, 128);
        load_tile(qb + 4*FA_TILE, Vg, 128);
        asm volatile("cp.async.commit_group;\n" ::);
    }

    float o[16][4];
#pragma unroll
    for (int i = 0; i < 16; i++)
#pragma unroll
        for (int r = 0; r < 4; r++) o[i][r] = 0.f;
    float m1 = -1e30f, m2 = -1e30f, l1 = 0.f, l2 = 0.f;
    uint32_t q[8][4];
    bool qloaded = false;

    const int tr1 = wm + (lane >> 2);
    const int cbase = (lane & 3) * 2;

    for (int j = 0; j <= mi; j++) {
        if (j + 1 <= mi) asm volatile("cp.async.wait_group 1;\n" ::: "memory");
        else             asm volatile("cp.async.wait_group 0;\n" ::: "memory");
        __syncthreads();
        if (!qloaded) {
#pragma unroll
            for (int kt = 0; kt < 8; kt++) {
                uint32_t ad = qb + (uint32_t)(wm + (g & 1) * 8 + ri) * FA_PITCH
                                 + kt * 32 + (g >> 1) * 16;
                ldsm4(q[kt], ad);
            }
            qloaded = true;
        }
        uint32_t kb = qb + FA_TILE + (uint32_t)(j & 1) * FA_TILE;
        uint32_t vb = qb + 3*FA_TILE + (uint32_t)(j & 1) * FA_TILE;

        float c[16][4];
#pragma unroll
        for (int i = 0; i < 16; i++) { c[i][0]=0.f; c[i][1]=0.f; c[i][2]=0.f; c[i][3]=0.f; }
#pragma unroll
        for (int kt = 0; kt < 8; kt++) {
#pragma unroll
            for (int np = 0; np < 8; np++) {
                uint32_t rr[4], b0[2], b1[2];
                uint32_t bd = kb + (uint32_t)(np * 16 + (g & 1) * 8 + ri) * FA_PITCH
                                 + kt * 32 + (g >> 1) * 16;
                ldsm4(rr, bd);
                b0[0] = rr[0]; b0[1] = rr[2];
                b1[0] = rr[1]; b1[1] = rr[3];
                mma_f16(c[np * 2],     q[kt], b0);
                mma_f16(c[np * 2 + 1], q[kt], b1);
            }
        }

        const bool diag = (j == mi);
        float mx1 = -1e30f, mx2 = -1e30f;
#pragma unroll
        for (int nt = 0; nt < 16; nt++) {
            int cn = nt * 8 + cbase;
            float s0 = c[nt][0] * FASCALE, s1 = c[nt][1] * FASCALE;
            float s2 = c[nt][2] * FASCALE, s3 = c[nt][3] * FASCALE;
            if (diag) {
                if (cn     > tr1)     s0 = -1e30f;
                if (cn + 1 > tr1)     s1 = -1e30f;
                if (cn     > tr1 + 8) s2 = -1e30f;
                if (cn + 1 > tr1 + 8) s3 = -1e30f;
            }
            c[nt][0] = s0; c[nt][1] = s1; c[nt][2] = s2; c[nt][3] = s3;
            mx1 = fmaxf(mx1, fmaxf(s0, s1));
            mx2 = fmaxf(mx2, fmaxf(s2, s3));
        }
        mx1 = fmaxf(mx1, __shfl_xor_sync(0xffffffffu, mx1, 1));
        mx1 = fmaxf(mx1, __shfl_xor_sync(0xffffffffu, mx1, 2));
        mx2 = fmaxf(mx2, __shfl_xor_sync(0xffffffffu, mx2, 1));
        mx2 = fmaxf(mx2, __shfl_xor_sync(0xffffffffu, mx2, 2));

        float m1n = fmaxf(m1, mx1), m2n = fmaxf(m2, mx2);
        float corr1 = __expf(m1 - m1n), corr2 = __expf(m2 - m2n);
        float s1sum = 0.f, s2sum = 0.f;
#pragma unroll
        for (int nt = 0; nt < 16; nt++) {
            c[nt][0] = __expf(c[nt][0] - m1n);
            c[nt][1] = __expf(c[nt][1] - m1n);
            c[nt][2] = __expf(c[nt][2] - m2n);
            c[nt][3] = __expf(c[nt][3] - m2n);
            s1sum += c[nt][0] + c[nt][1];
            s2sum += c[nt][2] + c[nt][3];
        }
        s1sum += __shfl_xor_sync(0xffffffffu, s1sum, 1);
        s1sum += __shfl_xor_sync(0xffffffffu, s1sum, 2);
        s2sum += __shfl_xor_sync(0xffffffffu, s2sum, 1);
        s2sum += __shfl_xor_sync(0xffffffffu, s2sum, 2);
        l1 = l1 * corr1 + s1sum;
        l2 = l2 * corr2 + s2sum;
        m1 = m1n; m2 = m2n;
#pragma unroll
        for (int nt = 0; nt < 16; nt++) {
            o[nt][0] *= corr1; o[nt][1] *= corr1;
            o[nt][2] *= corr2; o[nt][3] *= corr2;
        }

#pragma unroll
        for (int kt = 0; kt < 8; kt++) {
            uint32_t a[4];
            a[0] = packh2(c[2*kt][0],   c[2*kt][1]);
            a[1] = packh2(c[2*kt][2],   c[2*kt][3]);
            a[2] = packh2(c[2*kt+1][0], c[2*kt+1][1]);
            a[3] = packh2(c[2*kt+1][2], c[2*kt+1][3]);
#pragma unroll
            for (int np = 0; np < 8; np++) {
                uint32_t rr[4], b0[2], b1[2];
                uint32_t bd = vb + (uint32_t)(kt * 16 + (g >> 1) * 8 + ri) * FA_PITCH
                                 + (np * 16 + (g & 1) * 8) * 2;
                ldsm4t(rr, bd);
                b0[0] = rr[0]; b0[1] = rr[2];
                b1[0] = rr[1]; b1[1] = rr[3];
                mma_f16(o[np * 2],     a, b0);
                mma_f16(o[np * 2 + 1], a, b1);
            }
        }
        __syncthreads();
        if (j + 2 <= mi) {
            load_tile(qb + FA_TILE + (uint32_t)(j & 1) * FA_TILE,   Kg, (j + 2) * 128);
            load_tile(qb + 3*FA_TILE + (uint32_t)(j & 1) * FA_TILE, Vg, (j + 2) * 128);
            asm volatile("cp.async.commit_group;\n" ::);
        }
    }

    // ---- epilogue: z1 += O/l (fp32, float2 RMW; disjoint per CTA) ----
    float inv1 = 1.f / l1, inv2 = 1.f / l2;
    int b = bh / NH, h = bh % NH;
    int kk2 = h % 3, nn = h / 3;
    int slot = g_slot[kk2];
    int gm1 = m0 + tr1;
#pragma unroll
    for (int nt = 0; nt < 16; nt++) {
        int e = slot * DH + nt * 8 + cbase;
        size_t i1 = (((size_t)(b * TT + gm1))     * N4 + nn) * DD + e;
        size_t i2 = (((size_t)(b * TT + gm1 + 8)) * N4 + nn) * DD + e;
        float2* q1 = (float2*)(g_z1 + i1);
        float2* q2 = (float2*)(g_z1 + i2);
        float2 c1 = *q1, c2 = *q2;
        *q1 = make_float2(c1.x + o[nt][0] * inv1, c1.y + o[nt][1] * inv1);
        *q2 = make_float2(c2.x + o[nt][2] * inv2, c2.y + o[nt][3] * inv2);
    }
}

// ================= fp16 HMMA NT GEMM (BK=32, 3-stage, 8 warps x 32x64) =================
#define H3_TILE  10240
#define H3_STAGE (2*H3_TILE)
#define H3_SMEM  (3*H3_STAGE)

template<class Epi>
__global__ void __launch_bounds__(256, 2)
hgemm(const __half* __restrict__ A, const __half* __restrict__ B,
      int M, int N, int Kd, int lda, int ldb, long sA, long sB, Epi epi)
{
    extern __shared__ char hsm[];
    const int bz = blockIdx.z;
    A += (size_t)bz * sA;
    B += (size_t)bz * sB;
    const int m0 = blockIdx.y * 128, n0 = blockIdx.x * 128;
    const int tid = threadIdx.x;
    const int lane = tid & 31, wid = tid >> 5;
    const int wm = (wid & 3) * 32, wn = (wid >> 2) * 64;

    float c[16][4];
#pragma unroll
    for (int i = 0; i < 16; i++)
#pragma unroll
        for (int j = 0; j < 4; j++) c[i][j] = 0.f;

    {
        int nt = Kd >> 5;
        auto issue = [&](int t) {
            uint32_t base_b = (uint32_t)__cvta_generic_to_shared(hsm + (t % 3) * H3_STAGE);
            const __half* p;
            uint32_t dst;
            if (tid < 128) {
                p = A + (size_t)(m0 + tid) * lda + t * 32;
                dst = base_b + (uint32_t)tid * 80;
            } else {
                p = B + (size_t)(n0 + tid - 128) * ldb + t * 32;
                dst = base_b + H3_TILE + (uint32_t)(tid - 128) * 80;
            }
#pragma unroll
            for (int i = 0; i < 4; i++) cp16(dst + i * 16, p + i * 8);
            asm volatile("cp.async.commit_group;\n" ::);
        };

        issue(0);
        if (nt > 1) issue(1);
        const int g = lane >> 3, ri = lane & 7;
        for (int t = 0; t < nt; t++) {
            if (t == nt - 1) asm volatile("cp.async.wait_group 0;\n" ::: "memory");
            else             asm volatile("cp.async.wait_group 1;\n" ::: "memory");
            __syncthreads();
            if (t + 2 < nt) issue(t + 2);

            uint32_t as_b = (uint32_t)__cvta_generic_to_shared(hsm + (t % 3) * H3_STAGE);
            uint32_t bs_b = as_b + H3_TILE;
#pragma unroll
            for (int ks = 0; ks < 2; ks++) {
                uint32_t a[2][4];
#pragma unroll
                for (int mt = 0; mt < 2; mt++) {
                    uint32_t ad = as_b + (uint32_t)(wm + mt * 16 + (g & 1) * 8 + ri) * 80
                                       + ks * 32 + (g >> 1) * 16;
                    ldsm4(a[mt], ad);
                }
#pragma unroll
                for (int np = 0; np < 4; np++) {
                    uint32_t rr[4], b0[2], b1[2];
                    uint32_t bd = bs_b + (uint32_t)(wn + np * 16 + (g & 1) * 8 + ri) * 80
                                       + ks * 32 + (g >> 1) * 16;
                    ldsm4(rr, bd);
                    b0[0] = rr[0]; b0[1] = rr[2];
                    b1[0] = rr[1]; b1[1] = rr[3];
#pragma unroll
                    for (int mt = 0; mt < 2; mt++) {
                        mma_f16(c[mt * 8 + 2*np],     a[mt], b0);
                        mma_f16(c[mt * 8 + 2*np + 1], a[mt], b1);
                    }
                }
            }
        }
    }
    // ---- vectorized pair epilogue ----
#pragma unroll
    for (int mt = 0; mt < 2; mt++)
#pragma unroll
        for (int nt8 = 0; nt8 < 8; nt8++) {
            int gm = m0 + wm + mt * 16 + (lane >> 2);
            int gn = n0 + wn + nt8 * 8 + (lane & 3) * 2;
            epi(gm,     gn, bz, c[mt * 8 + nt8][0], c[mt * 8 + nt8][1]);
            epi(gm + 8, gn, bz, c[mt * 8 + nt8][2], c[mt * 8 + nt8][3]);
        }
}

// ---------------- LN over 128 per (bt, k, n) -> x_head (fp16 out) ----------------
__global__ void k_ln_head(const float* __restrict__ sc, const float* __restrict__ bi) {
    int bt = blockIdx.x, z = blockIdx.y;
    int kk = z >> 2, n = z & 3;
    int ns = g_invp[kk][n];
    int slot = g_slot[kk];
    const float* src = g_z1 + ((size_t)bt * 4 + ns) * DD + slot * DH;
    int tid = threadIdx.x;
    __shared__ float red[4];
    float v = src[tid];
    float mu = block_sum<4>(v, red) * (1.f / 128.f);
    float d = v - mu;
    float var = block_sum<4>(d * d, red) * (1.f / 128.f);
    g_xhh[((size_t)bt * NH + z) * DH + tid] =
        __float2half_rn(d * rsqrtf(var + EPSF) * sc[tid] + bi[tid]);
}

// ---------------- LN over 896 (fp16 out, feeds mixer1) ----------------
__global__ void k_ln_mixer(const float* __restrict__ sc, const float* __restrict__ bi) {
    __shared__ float red[8];
    size_t row = blockIdx.x;
    const float* src = g_z1 + row * DD;
    __half* dst = g_hmh + row * DD;
    int tid = threadIdx.x;
    float v[4];
    float s = 0.f;
#pragma unroll
    for (int i = 0; i < 4; i++) {
        int c = tid + i * 256;
        v[i] = (c < DD) ? src[c] : 0.f;
        s += v[i];
    }
    s = block_sum<8>(s, red);
    float mu = s * (1.f / 896.f);
    float q = 0.f;
#pragma unroll
    for (int i = 0; i < 4; i++) {
        int c = tid + i * 256;
        if (c < DD) { float d = v[i] - mu; q += d * d; }
    }
    q = block_sum<8>(q, red);
    float r = rsqrtf(q * (1.f / 896.f) + EPSF);
#pragma unroll
    for (int i = 0; i < 4; i++) {
        int c = tid + i * 256;
        if (c < DD) dst[c] = __float2half_rn((v[i] - mu) * r * sc[c] + bi[c]);
    }
}

// ---------------- LN over 3584 (fp16 in from z2h, fp16 out to g_hmh) ----------------
__global__ void k_ln_dec(const float* __restrict__ sc, const float* __restrict__ bi) {
    __shared__ float red[8];
    size_t row = blockIdx.x;
    const __half* src = g_z2h + row * NDD;
    __half* dst = g_hmh + row * NDD;
    int tid = threadIdx.x;
    float v[14];
    float s = 0.f;
#pragma unroll
    for (int i = 0; i < 14; i++) { v[i] = __half2float(src[tid + i * 256]); s += v[i]; }
    s = block_sum<8>(s, red);
    float mu = s * (1.f / 3584.f);
    float q = 0.f;
#pragma unroll
    for (int i = 0; i < 14; i++) { float d = v[i] - mu; q += d * d; }
    q = block_sum<8>(q, red);
    float r = rsqrtf(q * (1.f / 3584.f) + EPSF);
#pragma unroll
    for (int i = 0; i < 14; i++) {
        int c = tid + i * 256;
        dst[c] = __float2half_rn((v[i] - mu) * r * sc[c] + bi[c]);
    }
}

// ---------------- host launch ----------------
static inline void* sym_addr(const void* symbol) {
    void* p = nullptr;
    cudaGetSymbolAddress(&p, symbol);
    return p;
}

extern "C" void kernel_launch(void* const* d_in, const int* in_sizes, int n_in,
                              void* d_out, int out_size) {
    (void)in_sizes; (void)n_in; (void)out_size;
    const float* x          = (const float*)d_in[0];
    const float* enc_base_w = (const float*)d_in[1];
    const float* enc_A_w    = (const float*)d_in[2];
    const float* enc_B      = (const float*)d_in[3];
    const float* enc_beta   = (const float*)d_in[4];
    const float* Wqkv       = (const float*)d_in[5];
    const float* ln_attn_s  = (const float*)d_in[6];
    const float* ln_attn_b  = (const float*)d_in[7];
    const float* ln_mix_s   = (const float*)d_in[8];
    const float* ln_mix_b   = (const float*)d_in[9];
    const float* w1         = (const float*)d_in[10];
    const float* b1         = (const float*)d_in[11];
    const float* w2         = (const float*)d_in[12];
    const float* b2         = (const float*)d_in[13];
    const float* dls        = (const float*)d_in[14];
    const float* dlb        = (const float*)d_in[15];
    const float* down       = (const float*)d_in[16];
    const float* up         = (const float*)d_in[17];
    const int*   phase      = (const int*)d_in[18];
    float* out = (float*)d_out;

    __half* p_h    = (__half*)sym_addr(g_h);
    __half* p_hmh  = (__half*)sym_addr(g_hmh);
    __half* p_hid  = (__half*)sym_addr(g_hidden);
    __half* p_xhh  = (__half*)sym_addr(g_xhh);
    __half* p_decH = (__half*)sym_addr(g_decH);
    __half* p_xH   = (__half*)sym_addr(g_xH);
    __half* p_wbA  = (__half*)sym_addr(g_wbA);
    __half* p_ebT  = (__half*)sym_addr(g_ebT);
    __half* p_wqT  = (__half*)sym_addr(g_wqT);
    __half* p_w1H  = (__half*)sym_addr(g_w1H);
    __half* p_w2H  = (__half*)sym_addr(g_w2H);
    __half* p_down = (__half*)sym_addr(g_downH);
    __half* p_upH  = (__half*)sym_addr(g_upH);

    // dynamic smem caps (idempotent)
    cudaFuncSetAttribute(hgemm<EpiBaseH>, cudaFuncAttributeMaxDynamicSharedMemorySize, H3_SMEM);
    cudaFuncSetAttribute(hgemm<EpiDelta>, cudaFuncAttributeMaxDynamicSharedMemorySize, H3_SMEM);
    cudaFuncSetAttribute(hgemm<EpiQKV  >, cudaFuncAttributeMaxDynamicSharedMemorySize, H3_SMEM);
    cudaFuncSetAttribute(hgemm<EpiGelu >, cudaFuncAttributeMaxDynamicSharedMemorySize, H3_SMEM);
    cudaFuncSetAttribute(hgemm<EpiMix2 >, cudaFuncAttributeMaxDynamicSharedMemorySize, H3_SMEM);
    cudaFuncSetAttribute(hgemm<EpiDec4 >, cudaFuncAttributeMaxDynamicSharedMemorySize, H3_SMEM);
    cudaFuncSetAttribute(hgemm<EpiOut  >, cudaFuncAttributeMaxDynamicSharedMemorySize, H3_SMEM);
    cudaFuncSetAttribute(k_flash, cudaFuncAttributeMaxDynamicSharedMemorySize, FA_SMEM);

    // 0. scalars + phase tables
    k_scalars<<<1, 1>>>(enc_beta, phase);

    // 1. fused packing (single launch)
    k_pack<<<(PTOT + 255)/256, 256>>>(x, enc_base_w, w1, w2, up, enc_B, Wqkv, down, enc_A_w);

    // 2. [base | h] = x @ [wb ; enc_A]^T  (merged)
    hgemm<<<dim3(8, 64, 1), 256, H3_SMEM>>>(
        p_xH, p_wbA, BTOK, 1024, IOD, IOD, IOD, 0, 0, EpiBaseH{});

    // 3. z1 = base + beta*(h @ enc_B)  (fp16 NT, K=64, fp32 z1, float2 stores)
    hgemm<<<dim3(28, 64, 1), 256, H3_SMEM>>>(
        p_h, p_ebT, BTOK, NDD, RNK, RNK, RNK, 0, 0, EpiDelta{});

    // 4. LN over slot heads -> x_head (fp16)
    k_ln_head<<<dim3(BTOK, NH), 128>>>(ln_attn_s, ln_attn_b);

    // 5. qkv (NT, batched 12)
    hgemm<<<dim3(3, 64, 12), 256, H3_SMEM>>>(
        p_xhh, p_wqT, BTOK, 3 * DH, DH, NH * DH, DH,
        (long)DH, (long)(3 * DH) * DH, EpiQKV{});

    // 6. flash attention (causal) -> fp32 float2 RMW into z1
    k_flash<<<dim3(8, BB * NH), 256, FA_SMEM>>>();

    // 7. mixer LN -> fp16
    k_ln_mixer<<<dim3(BTOK * N4), 256>>>(ln_mix_s, ln_mix_b);

    // 8. hidden = gelu(hm @ w1.T + b1)  (NT)
    hgemm<<<dim3(28, 256, 1), 256, H3_SMEM>>>(
        p_hmh, p_w1H, BTOK * N4, HID, DD, DD, DD, 0, 0, EpiGelu{b1});

    // 9. z2 = z1 + hidden @ w2.T + b2  (NT, fp16 out)
    hgemm<<<dim3(7, 256, 1), 256, H3_SMEM>>>(
        p_hid, p_w2H, BTOK * N4, DD, HID, HID, HID, 0, 0, EpiMix2{b2});

    // 10. decoder LN (fp16 in/out)
    k_ln_dec<<<dim3(BTOK), 256>>>(dls, dlb);

    // 11. dec partials = catln @ down^T  (fp16 NT, 4-way split-K)
    hgemm<<<dim3(1, 64, 4), 256, H3_SMEM>>>(
        p_hmh, p_down, BTOK, 128, NDD / 4, NDD, NDD,
        (long)(NDD / 4), (long)(NDD / 4), EpiDec4{});

    // 11b. dec = sum of 4 split partials -> fp16
    k_decsum<<<(BTOK*RNK + 255)/256, 256>>>(BTOK*RNK);

    // 12. y = dec @ up^T  (fp16 NT, K=64, fp32 out, float2 stores)
    hgemm<<<dim3(8, 64, 1), 256, H3_SMEM>>>(
        p_decH, p_upH, BTOK, IOD, RNK, RNK, RNK, 0, 0, EpiOut{out});
}